// round 1
// baseline (speedup 1.0000x reference)
#include <cuda_runtime.h>
#include <cuda_bf16.h>

// Problem constants
#define NN      4000        // nodes (batch*neurons)
#define TT      32          // time steps
#define HH      64          // hidden
#define G3      192         // 3*H
#define EE      1024000     // edges
#define NTT     128000      // NN*TT
#define NNEUR   500
#define BB      8
#define NSLOT   256         // BB*TT
#define NSTEPS  12

// GRU kernel tiling
#define GRU_M       16      // rows per block
#define GRU_THREADS 256
#define WPAD        193     // 192 + 1 padding (conflict-free)
#define GRU_SMEM_FLOATS (64*WPAD*2 + 192*2 + GRU_M*64*2)
#define GRU_SMEM_BYTES  (GRU_SMEM_FLOATS * 4)

// ---------------- device scratch (static globals: allowed) ----------------
__device__ float g_buf[NTT * HH];      // GRU output, [NT, 64], 32.7MB (L2-resident)
__device__ float g_deg[NTT];           // degree -> then dis = rsqrt(deg) in place
__device__ float g_S_pre[NSLOT * HH];  // gathered sums (pre gcn_W)
__device__ float g_S[NSLOT * HH];      // post gcn_W

__device__ __forceinline__ float sigmoidf_(float x) {
    return 1.0f / (1.0f + __expf(-x));
}

// slot for node-time index nt, replicating torch .view scrambled reshape:
//   n = nt/32, t = nt%32, b = n/500, u = n%500, q = u*32+t, t' = q/500
//   slot = b*32 + t'
__device__ __forceinline__ int slot_of(int nt) {
    int n = nt >> 5;
    int t = nt & 31;
    int b = n / NNEUR;
    int u = n - b * NNEUR;
    int q = (u << 5) + t;      // < 16000
    return (b << 5) + q / NNEUR;
}

// ---------------- init ----------------
__global__ void init_kernel() {
    int i = blockIdx.x * blockDim.x + threadIdx.x;
    if (i < NTT) g_deg[i] = 1.0f;               // self-loop weight baked in
    if (i < NSLOT * HH) g_S_pre[i] = 0.0f;
}

// ---------------- fused GRU (input proj + recurrence) ----------------
__global__ void gru_kernel(const float* __restrict__ nf,
                           const float* __restrict__ Wih,
                           const float* __restrict__ Whh,
                           const float* __restrict__ bih,
                           const float* __restrict__ bhh) {
    extern __shared__ float sm[];
    float* Wih_t = sm;                     // [64][193], Wih_t[k*193+j] = Wih[j*64+k]
    float* Whh_t = Wih_t + 64 * WPAD;
    float* bih_s = Whh_t + 64 * WPAD;      // 192
    float* bhh_s = bih_s + 192;            // 192
    float* x_sh  = bhh_s + 192;            // [M][64]
    float* h_sh  = x_sh + GRU_M * 64;      // [M][64]

    const int tid = threadIdx.x;

    // coalesced global read; padded shared write is conflict-free
    for (int idx = tid; idx < G3 * HH; idx += GRU_THREADS) {
        int j = idx / HH, k = idx - j * HH;
        Wih_t[k * WPAD + j] = Wih[idx];
        Whh_t[k * WPAD + j] = Whh[idx];
    }
    if (tid < G3) { bih_s[tid] = bih[tid]; bhh_s[tid] = bhh[tid]; }
    for (int idx = tid; idx < GRU_M * 64; idx += GRU_THREADS) h_sh[idx] = 0.0f;
    __syncthreads();

    const int i    = tid & 63;      // gate/hidden index
    const int grp  = tid >> 6;      // 0..3
    const int row0 = grp * 4;       // 4 rows per thread
    const int grow0 = blockIdx.x * GRU_M;

    for (int t = 0; t < TT; ++t) {
        // stage x_t for this block's rows (coalesced)
        for (int idx = tid; idx < GRU_M * 64; idx += GRU_THREADS) {
            int r = idx >> 6, h = idx & 63;
            x_sh[idx] = nf[((grow0 + r) * TT + t) * HH + h];
        }
        __syncthreads();

        float axr[4], axz[4], axn[4], ahr[4], ahz[4], ahn[4];
        const float br = bih_s[i], bz = bih_s[64 + i], bn = bih_s[128 + i];
        const float cr = bhh_s[i], cz = bhh_s[64 + i], cn = bhh_s[128 + i];
        #pragma unroll
        for (int rr = 0; rr < 4; ++rr) {
            axr[rr] = br; axz[rr] = bz; axn[rr] = bn;
            ahr[rr] = cr; ahz[rr] = cz; ahn[rr] = cn;
        }

        #pragma unroll
        for (int k4 = 0; k4 < HH; k4 += 4) {
            float xs[4][4], hs[4][4];
            #pragma unroll
            for (int rr = 0; rr < 4; ++rr) {
                float4 xv = *(const float4*)&x_sh[(row0 + rr) * 64 + k4];
                float4 hv = *(const float4*)&h_sh[(row0 + rr) * 64 + k4];
                xs[rr][0] = xv.x; xs[rr][1] = xv.y; xs[rr][2] = xv.z; xs[rr][3] = xv.w;
                hs[rr][0] = hv.x; hs[rr][1] = hv.y; hs[rr][2] = hv.z; hs[rr][3] = hv.w;
            }
            #pragma unroll
            for (int kk = 0; kk < 4; ++kk) {
                const int k = k4 + kk;
                const float wr = Wih_t[k * WPAD + i];
                const float wz = Wih_t[k * WPAD + 64 + i];
                const float wn = Wih_t[k * WPAD + 128 + i];
                const float ur = Whh_t[k * WPAD + i];
                const float uz = Whh_t[k * WPAD + 64 + i];
                const float un = Whh_t[k * WPAD + 128 + i];
                #pragma unroll
                for (int rr = 0; rr < 4; ++rr) {
                    axr[rr] += xs[rr][kk] * wr;
                    axz[rr] += xs[rr][kk] * wz;
                    axn[rr] += xs[rr][kk] * wn;
                    ahr[rr] += hs[rr][kk] * ur;
                    ahz[rr] += hs[rr][kk] * uz;
                    ahn[rr] += hs[rr][kk] * un;
                }
            }
        }
        __syncthreads();   // all reads of h_sh/x_sh done

        #pragma unroll
        for (int rr = 0; rr < 4; ++rr) {
            const int row = row0 + rr;
            float r = sigmoidf_(axr[rr] + ahr[rr]);
            float z = sigmoidf_(axz[rr] + ahz[rr]);
            float n = tanhf(axn[rr] + r * ahn[rr]);
            float hprev = h_sh[row * 64 + i];
            float hnew  = (1.0f - z) * n + z * hprev;
            h_sh[row * 64 + i] = hnew;
            g_buf[((grow0 + row) * TT + t) * HH + i] = hnew;
        }
        __syncthreads();   // h writes visible before next step's reads
    }
}

// ---------------- degree accumulation ----------------
__global__ void deg_kernel(const int* __restrict__ ei, const float* __restrict__ ea) {
    int e = blockIdx.x * blockDim.x + threadIdx.x;
    if (e < EE) atomicAdd(&g_deg[ei[EE + e]], ea[e]);   // dst row of edge_index
}

__global__ void dis_kernel() {
    int i = blockIdx.x * blockDim.x + threadIdx.x;
    if (i < NTT) g_deg[i] = rsqrtf(g_deg[i]);           // deg >= 1 always
}

// ---------------- edge + self-loop gather-reduce into S_pre ----------------
// 16 lanes per item; each lane handles one float4 of the 64-wide feature row.
__global__ void scatter_kernel(const int* __restrict__ ei, const float* __restrict__ ea) {
    int gid  = blockIdx.x * blockDim.x + threadIdx.x;
    int item = gid >> 4;
    int part = gid & 15;
    if (item >= EE + NTT) return;

    int src, slot;
    float c;
    if (item < EE) {
        int s = ei[item];
        int d = ei[EE + item];
        c = g_deg[s] * ea[item] * g_deg[d];   // dis[src]*w*dis[dst]
        src = s; slot = slot_of(d);
    } else {
        int i = item - EE;                    // self loop, weight 1
        float dis = g_deg[i];
        c = dis * dis;
        src = i; slot = slot_of(i);
    }

    float4 v = *(const float4*)&g_buf[src * HH + part * 4];
    float* dst = &g_S_pre[slot * HH + part * 4];
    asm volatile("red.global.add.v4.f32 [%0], {%1,%2,%3,%4};"
                 :: "l"(dst), "f"(v.x * c), "f"(v.y * c), "f"(v.z * c), "f"(v.w * c)
                 : "memory");
}

// ---------------- apply gcn_W (commuted past aggregation): S = S_pre @ W^T ----
__global__ void gcnw_kernel(const float* __restrict__ W) {
    const int s = blockIdx.x;
    const int j = threadIdx.x;   // 64 threads
    __shared__ float sp[64];
    sp[j] = g_S_pre[s * HH + j];
    __syncthreads();
    float acc = 0.0f;
    #pragma unroll
    for (int k = 0; k < HH; ++k) acc += sp[k] * W[j * HH + k];
    g_S[s * HH + j] = acc;
}

// ---------------- attention + pooling + head (single block) ----------------
__global__ void final_kernel(const float* __restrict__ W1, const float* __restrict__ W2,
                             const float* __restrict__ fcW, const float* __restrict__ fcb,
                             float* __restrict__ out) {
    __shared__ float xt[NSLOT];        // [B*T']
    __shared__ float hid[BB * 16];
    __shared__ float attn[NSLOT];
    __shared__ float pooled[BB * HH];

    const int tid = threadIdx.x;       // 256 threads

    // xt[b,t'] = mean over 500*64 values = sum_h S[slot,h] / 32000
    {
        float s = 0.0f;
        #pragma unroll
        for (int h = 0; h < HH; ++h) s += g_S[tid * HH + h];
        xt[tid] = s * (1.0f / 32000.0f);
    }
    __syncthreads();

    if (tid < BB * 16) {
        int b = tid >> 4, k = tid & 15;
        float a = 0.0f;
        #pragma unroll
        for (int t = 0; t < TT; ++t) a += xt[b * TT + t] * W1[k * TT + t];
        hid[tid] = fmaxf(a, 0.0f);
    }
    __syncthreads();

    {
        int b = tid >> 5, t = tid & 31;
        float a = 0.0f;
        #pragma unroll
        for (int k = 0; k < 16; ++k) a += hid[b * 16 + k] * W2[t * 16 + k];
        attn[tid] = sigmoidf_(a);
    }
    __syncthreads();

    for (int idx = tid; idx < BB * HH; idx += 256) {
        int b = idx >> 6, h = idx & 63;
        float a = 0.0f;
        #pragma unroll
        for (int t = 0; t < TT; ++t) a += attn[b * TT + t] * g_S[(b * TT + t) * HH + h];
        pooled[idx] = a;
    }
    __syncthreads();

    if (tid < BB * NSTEPS) {
        int b = tid / NSTEPS, j = tid - b * NSTEPS;
        float a = fcb[j];
        #pragma unroll
        for (int h = 0; h < HH; ++h) a += pooled[b * HH + h] * fcW[j * HH + h];
        out[b * NSTEPS + j] = a;
    }
}

// ---------------- launch ----------------
extern "C" void kernel_launch(void* const* d_in, const int* in_sizes, int n_in,
                              void* d_out, int out_size) {
    const float* nf   = (const float*)d_in[0];   // node_features [4000,32,64]
    const int*   ei   = (const int*)  d_in[1];   // edge_index [2,E]
    const float* ea   = (const float*)d_in[2];   // edge_attr [E]
    // d_in[3] = batch (unused by reference math)
    const float* Wih  = (const float*)d_in[4];
    const float* Whh  = (const float*)d_in[5];
    const float* bih  = (const float*)d_in[6];
    const float* bhh  = (const float*)d_in[7];
    const float* gcnW = (const float*)d_in[8];
    const float* W1   = (const float*)d_in[9];
    const float* W2   = (const float*)d_in[10];
    const float* fcW  = (const float*)d_in[11];
    const float* fcb  = (const float*)d_in[12];
    float* out = (float*)d_out;

    cudaFuncSetAttribute(gru_kernel, cudaFuncAttributeMaxDynamicSharedMemorySize,
                         GRU_SMEM_BYTES);

    init_kernel<<<(NTT + 255) / 256, 256>>>();
    gru_kernel<<<NN / GRU_M, GRU_THREADS, GRU_SMEM_BYTES>>>(nf, Wih, Whh, bih, bhh);
    deg_kernel<<<(EE + 255) / 256, 256>>>(ei, ea);
    dis_kernel<<<(NTT + 255) / 256, 256>>>();
    {
        long items = (long)(EE + NTT) * 16;
        int blocks = (int)((items + 255) / 256);
        scatter_kernel<<<blocks, 256>>>(ei, ea);
    }
    gcnw_kernel<<<NSLOT, 64>>>(gcnW);
    final_kernel<<<1, 256>>>(W1, W2, fcW, fcb, out);
}

// round 2
// speedup vs baseline: 1.0432x; 1.0432x over previous
#include <cuda_runtime.h>
#include <cuda_bf16.h>

// Problem constants
#define NN      4000
#define TT      32
#define HH      64
#define G3      192
#define EE      1024000
#define NTT     128000
#define NNEUR   500
#define BB      8
#define NSLOT   256
#define NSTEPS  12

// GRU tiling: 143 blocks (one wave on 148 SMs), 28 rows/block, 256 threads,
// 4 groups of 64 threads, 7 rows per thread.
#define GRU_M       28
#define GRU_BLOCKS  143
#define ROWS_PT     7
#define GRU_THREADS 256
// smem: 2 packed weights (32*192 u64 each) + biases + x/h tiles
#define GRU_SMEM_BYTES (2*(32*G3)*8 + 2*G3*4 + 2*GRU_M*HH*4)

#define REP 16   // scatter accumulator replicas

typedef unsigned long long ull;

// ---------------- device scratch ----------------
__device__ float g_buf[NTT * HH];          // GRU output [NT,64]
__device__ float g_deg[NTT];               // degree -> rsqrt in place
__device__ float g_S_rep[REP][NSLOT * HH]; // replicated pre-W accumulators
__device__ float g_S_pre[NSLOT * HH];
__device__ float g_S[NSLOT * HH];

__device__ __forceinline__ float sigmoidf_(float x) {
    return 1.0f / (1.0f + __expf(-x));
}

// packed f32x2 helpers
__device__ __forceinline__ ull pk(float a, float b) {
    ull r; asm("mov.b64 %0, {%1, %2};" : "=l"(r) : "f"(a), "f"(b)); return r;
}
__device__ __forceinline__ float2 upk(ull v) {
    float2 r; asm("mov.b64 {%0, %1}, %2;" : "=f"(r.x), "=f"(r.y) : "l"(v)); return r;
}
__device__ __forceinline__ ull ffma2(ull a, ull b, ull c) {
    ull d; asm("fma.rn.f32x2 %0, %1, %2, %3;" : "=l"(d) : "l"(a), "l"(b), "l"(c));
    return d;
}
__device__ __forceinline__ float psum(ull v) { float2 p = upk(v); return p.x + p.y; }

// slot for node-time index nt (torch .view scrambled reshape)
__device__ __forceinline__ int slot_of(int nt) {
    int n = nt >> 5;
    int t = nt & 31;
    int b = n / NNEUR;
    int u = n - b * NNEUR;
    int q = (u << 5) + t;
    return (b << 5) + q / NNEUR;
}

// ---------------- init ----------------
__global__ void init_kernel() {
    int i = blockIdx.x * blockDim.x + threadIdx.x;
    if (i < NTT) g_deg[i] = 1.0f;                       // self-loop baked in
    if (i < REP * NSLOT * HH) ((float*)g_S_rep)[i] = 0.0f;
}

// ---------------- fused GRU, packed f32x2 ----------------
__global__ void __launch_bounds__(GRU_THREADS, 1)
gru_kernel(const float* __restrict__ nf,
           const float* __restrict__ Wih,
           const float* __restrict__ Whh,
           const float* __restrict__ bih,
           const float* __restrict__ bhh) {
    extern __shared__ char smraw[];
    ull*   WI    = (ull*)smraw;                   // [32][192] packed k-pairs
    ull*   WH    = WI + 32 * G3;
    float* bih_s = (float*)(WH + 32 * G3);        // 192
    float* bhh_s = bih_s + G3;                    // 192
    float* x_sh  = bhh_s + G3;                    // [28][64]
    float* h_sh  = x_sh + GRU_M * HH;             // [28][64]

    const int tid = threadIdx.x;

    // pack weights: WI[kp*192 + j] = {Wih[j][2kp], Wih[j][2kp+1]}
    for (int idx = tid; idx < 32 * G3; idx += GRU_THREADS) {
        int kp = idx / G3, j = idx - kp * G3;
        WI[idx] = pk(Wih[j * HH + 2 * kp], Wih[j * HH + 2 * kp + 1]);
        WH[idx] = pk(Whh[j * HH + 2 * kp], Whh[j * HH + 2 * kp + 1]);
    }
    if (tid < G3) { bih_s[tid] = bih[tid]; bhh_s[tid] = bhh[tid]; }
    for (int idx = tid; idx < GRU_M * HH; idx += GRU_THREADS) h_sh[idx] = 0.0f;
    __syncthreads();

    const int i     = tid & 63;          // hidden index
    const int grp   = tid >> 6;          // 0..3
    const int row0  = grp * ROWS_PT;     // 7 rows per thread
    const int grow0 = blockIdx.x * GRU_M;

    const float br = bih_s[i],      bz = bih_s[64 + i],  bn = bih_s[128 + i];
    const float cr = bhh_s[i],      cz = bhh_s[64 + i],  cn = bhh_s[128 + i];

    for (int t = 0; t < TT; ++t) {
        for (int idx = tid; idx < GRU_M * HH; idx += GRU_THREADS) {
            int r = idx >> 6, h = idx & 63;
            int grow = grow0 + r; if (grow >= NN) grow = NN - 1;
            x_sh[idx] = nf[(grow * TT + t) * HH + h];
        }
        __syncthreads();

        ull acc[ROWS_PT][6];
        #pragma unroll
        for (int r = 0; r < ROWS_PT; ++r)
            #pragma unroll
            for (int g = 0; g < 6; ++g) acc[r][g] = 0ULL;

        #pragma unroll 4
        for (int kq = 0; kq < 16; ++kq) {
            const int kp0 = 2 * kq;
            // 12 packed weights (LDS.64, lane-consecutive, conflict-free)
            ull wr0 = WI[kp0 * G3 + i],            wr1 = WI[(kp0 + 1) * G3 + i];
            ull wz0 = WI[kp0 * G3 + 64 + i],       wz1 = WI[(kp0 + 1) * G3 + 64 + i];
            ull wn0 = WI[kp0 * G3 + 128 + i],      wn1 = WI[(kp0 + 1) * G3 + 128 + i];
            ull ur0 = WH[kp0 * G3 + i],            ur1 = WH[(kp0 + 1) * G3 + i];
            ull uz0 = WH[kp0 * G3 + 64 + i],       uz1 = WH[(kp0 + 1) * G3 + 64 + i];
            ull un0 = WH[kp0 * G3 + 128 + i],      un1 = WH[(kp0 + 1) * G3 + 128 + i];

            #pragma unroll
            for (int r = 0; r < ROWS_PT; ++r) {
                float4 xq = *(const float4*)&x_sh[(row0 + r) * HH + kq * 4];
                float4 hq = *(const float4*)&h_sh[(row0 + r) * HH + kq * 4];
                ull x0 = pk(xq.x, xq.y), x1 = pk(xq.z, xq.w);
                ull h0 = pk(hq.x, hq.y), h1 = pk(hq.z, hq.w);
                acc[r][0] = ffma2(x0, wr0, acc[r][0]);
                acc[r][1] = ffma2(x0, wz0, acc[r][1]);
                acc[r][2] = ffma2(x0, wn0, acc[r][2]);
                acc[r][3] = ffma2(h0, ur0, acc[r][3]);
                acc[r][4] = ffma2(h0, uz0, acc[r][4]);
                acc[r][5] = ffma2(h0, un0, acc[r][5]);
                acc[r][0] = ffma2(x1, wr1, acc[r][0]);
                acc[r][1] = ffma2(x1, wz1, acc[r][1]);
                acc[r][2] = ffma2(x1, wn1, acc[r][2]);
                acc[r][3] = ffma2(h1, ur1, acc[r][3]);
                acc[r][4] = ffma2(h1, uz1, acc[r][4]);
                acc[r][5] = ffma2(h1, un1, acc[r][5]);
            }
        }
        __syncthreads();   // all reads of h_sh/x_sh done

        #pragma unroll
        for (int r = 0; r < ROWS_PT; ++r) {
            float xr = psum(acc[r][0]) + br;
            float xz = psum(acc[r][1]) + bz;
            float xn = psum(acc[r][2]) + bn;
            float hr = psum(acc[r][3]) + cr;
            float hz = psum(acc[r][4]) + cz;
            float hn = psum(acc[r][5]) + cn;
            float rg = sigmoidf_(xr + hr);
            float zg = sigmoidf_(xz + hz);
            float ng = tanhf(xn + rg * hn);
            int row = row0 + r;
            float hprev = h_sh[row * HH + i];
            float hnew  = (1.0f - zg) * ng + zg * hprev;
            h_sh[row * HH + i] = hnew;
            int grow = grow0 + row;
            if (grow < NN) g_buf[(grow * TT + t) * HH + i] = hnew;
        }
        __syncthreads();
    }
}

// ---------------- degree ----------------
__global__ void deg_kernel(const int* __restrict__ ei, const float* __restrict__ ea) {
    int e = blockIdx.x * blockDim.x + threadIdx.x;
    if (e < EE) atomicAdd(&g_deg[ei[EE + e]], ea[e]);
}

__global__ void dis_kernel() {
    int i = blockIdx.x * blockDim.x + threadIdx.x;
    if (i < NTT) g_deg[i] = rsqrtf(g_deg[i]);
}

// ---------------- edge + self-loop gather-reduce (replicated targets) ----------
__global__ void scatter_kernel(const int* __restrict__ ei, const float* __restrict__ ea) {
    int gid  = blockIdx.x * blockDim.x + threadIdx.x;
    int item = gid >> 4;
    int part = gid & 15;
    if (item >= EE + NTT) return;
    int rep = blockIdx.x & (REP - 1);

    int src, slot;
    float c;
    if (item < EE) {
        int s = ei[item];
        int d = ei[EE + item];
        c = g_deg[s] * ea[item] * g_deg[d];
        src = s; slot = slot_of(d);
    } else {
        int i = item - EE;
        float dis = g_deg[i];
        c = dis * dis;
        src = i; slot = slot_of(i);
    }

    float4 v = *(const float4*)&g_buf[src * HH + part * 4];
    float* dst = &g_S_rep[rep][slot * HH + part * 4];
    asm volatile("red.global.add.v4.f32 [%0], {%1,%2,%3,%4};"
                 :: "l"(dst), "f"(v.x * c), "f"(v.y * c), "f"(v.z * c), "f"(v.w * c)
                 : "memory");
}

__global__ void reduce_rep_kernel() {
    int i = blockIdx.x * blockDim.x + threadIdx.x;   // 16384
    if (i >= NSLOT * HH) return;
    float s = 0.0f;
    #pragma unroll
    for (int r = 0; r < REP; ++r) s += g_S_rep[r][i];
    g_S_pre[i] = s;
}

// ---------------- apply gcn_W (commuted): S = S_pre @ W^T ----------------
__global__ void gcnw_kernel(const float* __restrict__ W) {
    const int s = blockIdx.x;
    const int j = threadIdx.x;
    __shared__ float sp[64];
    sp[j] = g_S_pre[s * HH + j];
    __syncthreads();
    float acc = 0.0f;
    #pragma unroll
    for (int k = 0; k < HH; ++k) acc += sp[k] * W[j * HH + k];
    g_S[s * HH + j] = acc;
}

// ---------------- attention + pooling + head ----------------
__global__ void final_kernel(const float* __restrict__ W1, const float* __restrict__ W2,
                             const float* __restrict__ fcW, const float* __restrict__ fcb,
                             float* __restrict__ out) {
    __shared__ float xt[NSLOT];
    __shared__ float hid[BB * 16];
    __shared__ float attn[NSLOT];
    __shared__ float pooled[BB * HH];

    const int tid = threadIdx.x;   // 256

    {
        float s = 0.0f;
        #pragma unroll
        for (int h = 0; h < HH; ++h) s += g_S[tid * HH + h];
        xt[tid] = s * (1.0f / 32000.0f);
    }
    __syncthreads();

    if (tid < BB * 16) {
        int b = tid >> 4, k = tid & 15;
        float a = 0.0f;
        #pragma unroll
        for (int t = 0; t < TT; ++t) a += xt[b * TT + t] * W1[k * TT + t];
        hid[tid] = fmaxf(a, 0.0f);
    }
    __syncthreads();

    {
        int b = tid >> 5, t = tid & 31;
        float a = 0.0f;
        #pragma unroll
        for (int k = 0; k < 16; ++k) a += hid[b * 16 + k] * W2[t * 16 + k];
        attn[tid] = sigmoidf_(a);
    }
    __syncthreads();

    for (int idx = tid; idx < BB * HH; idx += 256) {
        int b = idx >> 6, h = idx & 63;
        float a = 0.0f;
        #pragma unroll
        for (int t = 0; t < TT; ++t) a += attn[b * TT + t] * g_S[(b * TT + t) * HH + h];
        pooled[idx] = a;
    }
    __syncthreads();

    if (tid < BB * NSTEPS) {
        int b = tid / NSTEPS, j = tid - b * NSTEPS;
        float a = fcb[j];
        #pragma unroll
        for (int h = 0; h < HH; ++h) a += pooled[b * HH + h] * fcW[j * HH + h];
        out[b * NSTEPS + j] = a;
    }
}

// ---------------- launch ----------------
extern "C" void kernel_launch(void* const* d_in, const int* in_sizes, int n_in,
                              void* d_out, int out_size) {
    const float* nf   = (const float*)d_in[0];
    const int*   ei   = (const int*)  d_in[1];
    const float* ea   = (const float*)d_in[2];
    const float* Wih  = (const float*)d_in[4];
    const float* Whh  = (const float*)d_in[5];
    const float* bih  = (const float*)d_in[6];
    const float* bhh  = (const float*)d_in[7];
    const float* gcnW = (const float*)d_in[8];
    const float* W1   = (const float*)d_in[9];
    const float* W2   = (const float*)d_in[10];
    const float* fcW  = (const float*)d_in[11];
    const float* fcb  = (const float*)d_in[12];
    float* out = (float*)d_out;

    cudaFuncSetAttribute(gru_kernel, cudaFuncAttributeMaxDynamicSharedMemorySize,
                         GRU_SMEM_BYTES);

    init_kernel<<<(REP * NSLOT * HH + 255) / 256, 256>>>();
    gru_kernel<<<GRU_BLOCKS, GRU_THREADS, GRU_SMEM_BYTES>>>(nf, Wih, Whh, bih, bhh);
    deg_kernel<<<(EE + 255) / 256, 256>>>(ei, ea);
    dis_kernel<<<(NTT + 255) / 256, 256>>>();
    {
        long items = (long)(EE + NTT) * 16;
        int blocks = (int)((items + 255) / 256);
        scatter_kernel<<<blocks, 256>>>(ei, ea);
    }
    reduce_rep_kernel<<<(NSLOT * HH + 255) / 256, 256>>>();
    gcnw_kernel<<<NSLOT, 64>>>(gcnW);
    final_kernel<<<1, 256>>>(W1, W2, fcW, fcb, out);
}

// round 3
// speedup vs baseline: 1.8639x; 1.7867x over previous
#include <cuda_runtime.h>
#include <cuda_bf16.h>

// Problem constants
#define NN      4000
#define TT      32
#define HH      64
#define G3      192
#define EE      1024000
#define NTT     128000
#define NNEUR   500
#define BB      8
#define NSLOT   256
#define NSTEPS  12

// GRU mma tiling: 125 blocks x 32 rows, 256 threads (8 warps)
#define GM          32
#define GRU_BLOCKS  125
#define XPAD        68     // x/h smem row stride (conflict-free fragment loads)
#define GPAD        196    // gates smem row stride

// smem float offsets
#define OFF_XS   0                    // 2*32*68 = 4352
#define OFF_HS   4352                 // 32*68   = 2176
#define OFF_GX   6528                 // 32*196  = 6272
#define OFF_GH   12800                // 32*196  = 6272
#define OFF_BRZ  19072                // 128
#define OFF_BNI  19200                // 64
#define OFF_BNH  19264                // 64
#define OFF_DIS  19328                // 2*32 (double buffered)
#define GRU_SMEM_FLOATS 19392
#define GRU_SMEM_BYTES  (GRU_SMEM_FLOATS*4)

#define REP 16

// ---------------- device scratch ----------------
__device__ float g_buf[NTT * HH];          // GRU output pre-scaled by dis [NT,64]
__device__ float g_deg[NTT];               // degree -> rsqrt (dis) in place
__device__ float g_S_rep[REP][NSLOT * HH];
__device__ float g_S_pre[NSLOT * HH];
__device__ float g_S[NSLOT * HH];

__device__ __forceinline__ float sigmoidf_(float x) {
    return 1.0f / (1.0f + __expf(-x));
}

__device__ __forceinline__ unsigned tf32_(float f) {
    unsigned u; asm("cvt.rna.tf32.f32 %0, %1;" : "=r"(u) : "f"(f)); return u;
}
__device__ __forceinline__ float tf32f_(float f) {
    return __uint_as_float(tf32_(f));
}

__device__ __forceinline__ void mma1688(float* d, const unsigned* a, const unsigned* b) {
    asm volatile(
        "mma.sync.aligned.m16n8k8.row.col.f32.tf32.tf32.f32 "
        "{%0,%1,%2,%3}, {%4,%5,%6,%7}, {%8,%9}, {%0,%1,%2,%3};"
        : "+f"(d[0]), "+f"(d[1]), "+f"(d[2]), "+f"(d[3])
        : "r"(a[0]), "r"(a[1]), "r"(a[2]), "r"(a[3]), "r"(b[0]), "r"(b[1]));
}

// slot for node-time index nt (torch .view scrambled reshape)
__device__ __forceinline__ int slot_of(int nt) {
    int n = nt >> 5;
    int t = nt & 31;
    int b = n / NNEUR;
    int u = n - b * NNEUR;
    int q = (u << 5) + t;
    return (b << 5) + q / NNEUR;
}

// ---------------- init ----------------
__global__ void init_kernel() {
    int i = blockIdx.x * blockDim.x + threadIdx.x;
    if (i < NTT) g_deg[i] = 1.0f;                     // self-loop baked in
    if (i < REP * NSLOT * HH) ((float*)g_S_rep)[i] = 0.0f;
}

// ---------------- degree / dis (run BEFORE gru) ----------------
__global__ void deg_kernel(const int* __restrict__ ei, const float* __restrict__ ea) {
    int e = blockIdx.x * blockDim.x + threadIdx.x;
    if (e < EE) atomicAdd(&g_deg[ei[EE + e]], ea[e]);
}

__global__ void dis_kernel() {
    int i = blockIdx.x * blockDim.x + threadIdx.x;
    if (i < NTT) g_deg[i] = rsqrtf(g_deg[i]);
}

// ---------------- GRU via tf32 mma.sync ----------------
__global__ void __launch_bounds__(256, 1)
gru_kernel(const float* __restrict__ nf,
           const float* __restrict__ Wih,
           const float* __restrict__ Whh,
           const float* __restrict__ bih,
           const float* __restrict__ bhh) {
    extern __shared__ float sm[];
    float* xs    = sm + OFF_XS;
    float* hs    = sm + OFF_HS;
    float* gx    = sm + OFF_GX;
    float* gh    = sm + OFF_GH;
    float* brz   = sm + OFF_BRZ;
    float* bni   = sm + OFF_BNI;
    float* bnh   = sm + OFF_BNH;
    float* dis_s = sm + OFF_DIS;

    const int tid  = threadIdx.x;
    const int lane = tid & 31;
    const int w    = tid >> 5;          // warp 0..7
    const int gid  = lane >> 2;         // 0..7
    const int tig  = lane & 3;          // 0..3
    const int grow0 = blockIdx.x * GM;

    // biases (combined where possible)
    if (tid < 128) brz[tid] = bih[tid] + bhh[tid];
    if (tid < 64) { bni[tid] = bih[128 + tid]; bnh[tid] = bhh[128 + tid]; }
    for (int i = tid; i < GM * XPAD; i += 256) hs[i] = 0.0f;

    // register-resident weight fragments: B[p][n][k][2]
    unsigned B[2][3][8][2];
    #pragma unroll
    for (int n = 0; n < 3; ++n) {
        const int ncol = w * 24 + n * 8 + gid;
        #pragma unroll
        for (int k = 0; k < 8; ++k) {
            const int kr = k * 8 + tig;
            B[0][n][k][0] = tf32_(Wih[ncol * 64 + kr]);
            B[0][n][k][1] = tf32_(Wih[ncol * 64 + kr + 4]);
            B[1][n][k][0] = tf32_(Whh[ncol * 64 + kr]);
            B[1][n][k][1] = tf32_(Whh[ncol * 64 + kr + 4]);
        }
    }

    // x prefetch for t=0 (2 float4 per thread)
    const int r0v = tid >> 4,       c4 = (tid & 15) * 4;
    const int r1v = (tid + 256) >> 4;
    float4 xa = *(const float4*)&nf[((grow0 + r0v) * TT + 0) * HH + c4];
    float4 xb = *(const float4*)&nf[((grow0 + r1v) * TT + 0) * HH + c4];

    for (int t = 0; t < TT; ++t) {
        // stage x(t) tf32-rounded into buffer t&1
        float* xcur = xs + (t & 1) * (GM * XPAD);
        xcur[r0v * XPAD + c4 + 0] = tf32f_(xa.x);
        xcur[r0v * XPAD + c4 + 1] = tf32f_(xa.y);
        xcur[r0v * XPAD + c4 + 2] = tf32f_(xa.z);
        xcur[r0v * XPAD + c4 + 3] = tf32f_(xa.w);
        xcur[r1v * XPAD + c4 + 0] = tf32f_(xb.x);
        xcur[r1v * XPAD + c4 + 1] = tf32f_(xb.y);
        xcur[r1v * XPAD + c4 + 2] = tf32f_(xb.z);
        xcur[r1v * XPAD + c4 + 3] = tf32f_(xb.w);
        if (tid < 32) dis_s[(t & 1) * 32 + tid] = g_deg[(grow0 + tid) * TT + t];
        __syncthreads();

        // prefetch x(t+1)
        if (t + 1 < TT) {
            xa = *(const float4*)&nf[((grow0 + r0v) * TT + t + 1) * HH + c4];
            xb = *(const float4*)&nf[((grow0 + r1v) * TT + t + 1) * HH + c4];
        }

        // two GEMMs: p=0 x@Wih^T, p=1 h@Whh^T  -> acc[p][m2][n][4]
        float acc[2][2][3][4];
        #pragma unroll
        for (int p = 0; p < 2; ++p)
            #pragma unroll
            for (int m2 = 0; m2 < 2; ++m2)
                #pragma unroll
                for (int n = 0; n < 3; ++n)
                    #pragma unroll
                    for (int q = 0; q < 4; ++q) acc[p][m2][n][q] = 0.0f;

        #pragma unroll
        for (int k = 0; k < 8; ++k) {
            #pragma unroll
            for (int p = 0; p < 2; ++p) {
                const float* A = p ? hs : xcur;
                unsigned af[2][4];
                #pragma unroll
                for (int m2 = 0; m2 < 2; ++m2) {
                    const int rr = m2 * 16 + gid;
                    const int cc = k * 8 + tig;
                    af[m2][0] = __float_as_uint(A[rr * XPAD + cc]);
                    af[m2][1] = __float_as_uint(A[(rr + 8) * XPAD + cc]);
                    af[m2][2] = __float_as_uint(A[rr * XPAD + cc + 4]);
                    af[m2][3] = __float_as_uint(A[(rr + 8) * XPAD + cc + 4]);
                }
                #pragma unroll
                for (int m2 = 0; m2 < 2; ++m2)
                    #pragma unroll
                    for (int n = 0; n < 3; ++n)
                        mma1688(acc[p][m2][n], af[m2], B[p][n][k]);
            }
        }

        // store gate pre-activations
        #pragma unroll
        for (int p = 0; p < 2; ++p) {
            float* G = p ? gh : gx;
            #pragma unroll
            for (int m2 = 0; m2 < 2; ++m2) {
                #pragma unroll
                for (int n = 0; n < 3; ++n) {
                    const int rr = m2 * 16 + gid;
                    const int cb = w * 24 + n * 8 + 2 * tig;
                    G[rr * GPAD + cb]           = acc[p][m2][n][0];
                    G[rr * GPAD + cb + 1]       = acc[p][m2][n][1];
                    G[(rr + 8) * GPAD + cb]     = acc[p][m2][n][2];
                    G[(rr + 8) * GPAD + cb + 1] = acc[p][m2][n][3];
                }
            }
        }
        __syncthreads();

        // elementwise gates: thread owns (row, 8 consecutive i)
        const int row = tid >> 3;
        const int i0  = (tid & 7) * 8;
        const float dr = dis_s[(t & 1) * 32 + row];
        #pragma unroll
        for (int j = 0; j < 8; ++j) {
            const int i = i0 + j;
            float xr = gx[row * GPAD + i],       hr = gh[row * GPAD + i];
            float xz = gx[row * GPAD + 64 + i],  hz = gh[row * GPAD + 64 + i];
            float xn = gx[row * GPAD + 128 + i], hn = gh[row * GPAD + 128 + i];
            float rg = sigmoidf_(xr + hr + brz[i]);
            float zg = sigmoidf_(xz + hz + brz[64 + i]);
            float ng = tanhf(xn + bni[i] + rg * (hn + bnh[i]));
            float hp = hs[row * XPAD + i];
            float hnew = (1.0f - zg) * ng + zg * hp;
            hs[row * XPAD + i] = tf32f_(hnew);
            g_buf[((grow0 + row) * TT + t) * HH + i] = hnew * dr;  // pre-scale by dis
        }
        // next iteration's __syncthreads orders hs/gates reuse
    }
}

// ---------------- edge + self-loop gather-reduce ----------------
// g_buf rows are pre-scaled by dis[src]; per-edge factor = ea * dis[dst].
__global__ void scatter_kernel(const int* __restrict__ ei, const float* __restrict__ ea) {
    int gid  = blockIdx.x * blockDim.x + threadIdx.x;
    int item = gid >> 4;
    int part = gid & 15;
    if (item >= EE + NTT) return;
    int rep = blockIdx.x & (REP - 1);

    int src, slot;
    float c;
    if (item < EE) {
        int s = ei[item];
        int d = ei[EE + item];
        c = ea[item] * g_deg[d];
        src = s; slot = slot_of(d);
    } else {
        int i = item - EE;
        c = g_deg[i];
        src = i; slot = slot_of(i);
    }

    float4 v = *(const float4*)&g_buf[src * HH + part * 4];
    float* dst = &g_S_rep[rep][slot * HH + part * 4];
    asm volatile("red.global.add.v4.f32 [%0], {%1,%2,%3,%4};"
                 :: "l"(dst), "f"(v.x * c), "f"(v.y * c), "f"(v.z * c), "f"(v.w * c)
                 : "memory");
}

__global__ void reduce_rep_kernel() {
    int i = blockIdx.x * blockDim.x + threadIdx.x;
    if (i >= NSLOT * HH) return;
    float s = 0.0f;
    #pragma unroll
    for (int r = 0; r < REP; ++r) s += g_S_rep[r][i];
    g_S_pre[i] = s;
}

// ---------------- apply gcn_W (commuted): S = S_pre @ W^T ----------------
__global__ void gcnw_kernel(const float* __restrict__ W) {
    const int s = blockIdx.x;
    const int j = threadIdx.x;
    __shared__ float sp[64];
    sp[j] = g_S_pre[s * HH + j];
    __syncthreads();
    float acc = 0.0f;
    #pragma unroll
    for (int k = 0; k < HH; ++k) acc += sp[k] * W[j * HH + k];
    g_S[s * HH + j] = acc;
}

// ---------------- attention + pooling + head ----------------
__global__ void final_kernel(const float* __restrict__ W1, const float* __restrict__ W2,
                             const float* __restrict__ fcW, const float* __restrict__ fcb,
                             float* __restrict__ out) {
    __shared__ float xt[NSLOT];
    __shared__ float hid[BB * 16];
    __shared__ float attn[NSLOT];
    __shared__ float pooled[BB * HH];

    const int tid = threadIdx.x;   // 256

    {
        float s = 0.0f;
        #pragma unroll
        for (int h = 0; h < HH; ++h) s += g_S[tid * HH + h];
        xt[tid] = s * (1.0f / 32000.0f);
    }
    __syncthreads();

    if (tid < BB * 16) {
        int b = tid >> 4, k = tid & 15;
        float a = 0.0f;
        #pragma unroll
        for (int t = 0; t < TT; ++t) a += xt[b * TT + t] * W1[k * TT + t];
        hid[tid] = fmaxf(a, 0.0f);
    }
    __syncthreads();

    {
        int b = tid >> 5, t = tid & 31;
        float a = 0.0f;
        #pragma unroll
        for (int k = 0; k < 16; ++k) a += hid[b * 16 + k] * W2[t * 16 + k];
        attn[tid] = sigmoidf_(a);
    }
    __syncthreads();

    for (int idx = tid; idx < BB * HH; idx += 256) {
        int b = idx >> 6, h = idx & 63;
        float a = 0.0f;
        #pragma unroll
        for (int t = 0; t < TT; ++t) a += attn[b * TT + t] * g_S[(b * TT + t) * HH + h];
        pooled[idx] = a;
    }
    __syncthreads();

    if (tid < BB * NSTEPS) {
        int b = tid / NSTEPS, j = tid - b * NSTEPS;
        float a = fcb[j];
        #pragma unroll
        for (int h = 0; h < HH; ++h) a += pooled[b * HH + h] * fcW[j * HH + h];
        out[b * NSTEPS + j] = a;
    }
}

// ---------------- launch ----------------
extern "C" void kernel_launch(void* const* d_in, const int* in_sizes, int n_in,
                              void* d_out, int out_size) {
    const float* nf   = (const float*)d_in[0];
    const int*   ei   = (const int*)  d_in[1];
    const float* ea   = (const float*)d_in[2];
    const float* Wih  = (const float*)d_in[4];
    const float* Whh  = (const float*)d_in[5];
    const float* bih  = (const float*)d_in[6];
    const float* bhh  = (const float*)d_in[7];
    const float* gcnW = (const float*)d_in[8];
    const float* W1   = (const float*)d_in[9];
    const float* W2   = (const float*)d_in[10];
    const float* fcW  = (const float*)d_in[11];
    const float* fcb  = (const float*)d_in[12];
    float* out = (float*)d_out;

    cudaFuncSetAttribute(gru_kernel, cudaFuncAttributeMaxDynamicSharedMemorySize,
                         GRU_SMEM_BYTES);

    // order: deg/dis BEFORE gru (gru consumes dis); also puts gru at launch #4 for ncu
    init_kernel<<<(REP * NSLOT * HH + 255) / 256, 256>>>();
    deg_kernel<<<(EE + 255) / 256, 256>>>(ei, ea);
    dis_kernel<<<(NTT + 255) / 256, 256>>>();
    gru_kernel<<<GRU_BLOCKS, 256, GRU_SMEM_BYTES>>>(nf, Wih, Whh, bih, bhh);
    {
        long items = (long)(EE + NTT) * 16;
        int blocks = (int)((items + 255) / 256);
        scatter_kernel<<<blocks, 256>>>(ei, ea);
    }
    reduce_rep_kernel<<<(NSLOT * HH + 255) / 256, 256>>>();
    gcnw_kernel<<<NSLOT, 64>>>(gcnW);
    final_kernel<<<1, 256>>>(W1, W2, fcW, fcb, out);
}

// round 5
// speedup vs baseline: 2.7189x; 1.4587x over previous
#include <cuda_runtime.h>
#include <cuda_bf16.h>

// Problem constants
#define NN      4000
#define TT      32
#define HH      64
#define G3      192
#define EE      1024000
#define NTT     128000
#define NNEUR   500
#define BB      8
#define NSLOT   256
#define NSTEPS  12

#define GM          32     // rows per GRU block
#define GRU_BLOCKS  125
#define HPAD        72     // bf16 row stride (conflict-free ldmatrix)
#define REP 16

// ---------------- device scratch ----------------
__device__ __nv_bfloat16 g_buf[NTT * HH];  // GRU output pre-scaled by dis, bf16
__device__ float g_deg[NTT];               // degree -> rsqrt (dis) in place
__device__ float g_S_rep[REP][NSLOT * HH];
__device__ float g_S_pre[NSLOT * HH];
__device__ float g_S[NSLOT * HH];

// ---------------- helpers ----------------
__device__ __forceinline__ float tanha_(float x) {
    float y; asm("tanh.approx.f32 %0, %1;" : "=f"(y) : "f"(x)); return y;
}
__device__ __forceinline__ float siga_(float x) {
    return 0.5f * tanha_(0.5f * x) + 0.5f;
}
__device__ __forceinline__ float sigacc_(float x) {   // accurate sigmoid (final kernel)
    return 1.0f / (1.0f + __expf(-x));
}
// pack two floats into bf16x2 with memory order {lo=a, hi=b}
__device__ __forceinline__ unsigned bpack(float a, float b) {
    unsigned r;
    asm("cvt.rn.bf16x2.f32 %0, %1, %2;" : "=r"(r) : "f"(b), "f"(a));
    return r;
}
__device__ __forceinline__ void mma16816(float* d, const unsigned* a, const unsigned* b) {
    asm volatile(
        "mma.sync.aligned.m16n8k16.row.col.f32.bf16.bf16.f32 "
        "{%0,%1,%2,%3}, {%4,%5,%6,%7}, {%8,%9}, {%0,%1,%2,%3};"
        : "+f"(d[0]), "+f"(d[1]), "+f"(d[2]), "+f"(d[3])
        : "r"(a[0]), "r"(a[1]), "r"(a[2]), "r"(a[3]), "r"(b[0]), "r"(b[1]));
}
__device__ __forceinline__ void ldsm4_(unsigned* r, unsigned saddr) {
    asm volatile("ldmatrix.sync.aligned.m8n8.x4.shared.b16 {%0,%1,%2,%3}, [%4];"
                 : "=r"(r[0]), "=r"(r[1]), "=r"(r[2]), "=r"(r[3]) : "r"(saddr));
}

// slot for node-time index nt (torch .view scrambled reshape)
__device__ __forceinline__ int slot_of(int nt) {
    int n = nt >> 5;
    int t = nt & 31;
    int b = n / NNEUR;
    int u = n - b * NNEUR;
    int q = (u << 5) + t;
    return (b << 5) + q / NNEUR;
}

// ---------------- init ----------------
__global__ void init_kernel() {
    int i = blockIdx.x * blockDim.x + threadIdx.x;
    if (i < NTT) g_deg[i] = 1.0f;                      // self-loop baked in
    if (i < REP * NSLOT * HH) ((float*)g_S_rep)[i] = 0.0f;
}

// ---------------- degree / dis ----------------
__global__ void deg_kernel(const int* __restrict__ ei, const float* __restrict__ ea) {
    int e = blockIdx.x * blockDim.x + threadIdx.x;
    if (e < EE) atomicAdd(&g_deg[ei[EE + e]], ea[e]);
}

__global__ void dis_kernel() {
    int i = blockIdx.x * blockDim.x + threadIdx.x;
    if (i < NTT) g_deg[i] = rsqrtf(g_deg[i]);
}

// ---------------- GRU: bf16 mma + ldmatrix + register epilogue ----------------
__global__ void __launch_bounds__(256, 1)
gru_kernel(const float* __restrict__ nf,
           const float* __restrict__ Wih,
           const float* __restrict__ Whh,
           const float* __restrict__ bih,
           const float* __restrict__ bhh) {
    __shared__ __nv_bfloat16 xs[2][GM][HPAD];
    __shared__ __nv_bfloat16 hsm[2][GM][HPAD];
    __shared__ float dis_s[2][GM];

    const int tid  = threadIdx.x;
    const int lane = tid & 31;
    const int w    = tid >> 5;         // warp 0..7
    const int gid  = lane >> 2;        // 0..7
    const int tig  = lane & 3;         // 0..3
    const int grow0 = blockIdx.x * GM;

    // zero initial h buffer
    for (int i = tid; i < GM * HPAD; i += 256)
        ((__nv_bfloat16*)hsm[0])[i] = __float2bfloat16(0.0f);

    // B fragments: warp w owns cols g*64 + w*8 .. +7 for g in {r,z,n}
    unsigned Bf[2][3][4][2];
    #pragma unroll
    for (int g = 0; g < 3; ++g) {
        const int ncol = g * 64 + w * 8 + gid;
        #pragma unroll
        for (int kq = 0; kq < 4; ++kq) {
            const int k0 = kq * 16 + 2 * tig;
            Bf[0][g][kq][0] = bpack(Wih[ncol * 64 + k0],     Wih[ncol * 64 + k0 + 1]);
            Bf[0][g][kq][1] = bpack(Wih[ncol * 64 + k0 + 8], Wih[ncol * 64 + k0 + 9]);
            Bf[1][g][kq][0] = bpack(Whh[ncol * 64 + k0],     Whh[ncol * 64 + k0 + 1]);
            Bf[1][g][kq][1] = bpack(Whh[ncol * 64 + k0 + 8], Whh[ncol * 64 + k0 + 9]);
        }
    }

    // per-thread bias registers for output cols i0, i0+1
    const int i0 = w * 8 + 2 * tig;
    float br_[2], bz_[2], bnx_[2], bnh_[2];
    #pragma unroll
    for (int c = 0; c < 2; ++c) {
        br_[c]  = bih[i0 + c] + bhh[i0 + c];
        bz_[c]  = bih[64 + i0 + c] + bhh[64 + i0 + c];
        bnx_[c] = bih[128 + i0 + c];
        bnh_[c] = bhh[128 + i0 + c];
    }

    // x staging: thread -> (row = tid>>3, cols (tid&7)*8 .. +7)
    const int xrow = tid >> 3;
    const int xc   = (tid & 7) * 8;
    const float* nfrow = nf + ((size_t)(grow0 + xrow) * TT) * HH + xc;

    float4 xa = *(const float4*)(nfrow);
    float4 xb = *(const float4*)(nfrow + 4);
    {
        unsigned* xp = (unsigned*)&xs[0][xrow][xc];
        xp[0] = bpack(xa.x, xa.y); xp[1] = bpack(xa.z, xa.w);
        xp[2] = bpack(xb.x, xb.y); xp[3] = bpack(xb.z, xb.w);
    }
    if (tid < GM) dis_s[0][tid] = g_deg[(grow0 + tid) * TT + 0];

    // ldmatrix lane addressing
    const int ro = (lane & 7) + ((lane >> 3) & 1) * 8;
    const int kh = (lane >> 4) & 1;
    const unsigned lane_off = (unsigned)(ro * HPAD * 2 + kh * 16);
    const unsigned xs0 = (unsigned)__cvta_generic_to_shared(&xs[0][0][0]);
    const unsigned hs0 = (unsigned)__cvta_generic_to_shared(&hsm[0][0][0]);
    const unsigned bufstride = GM * HPAD * 2;

    float h_reg[8];
    #pragma unroll
    for (int i = 0; i < 8; ++i) h_reg[i] = 0.0f;

    __syncthreads();

    for (int t = 0; t < TT; ++t) {
        const int cur = t & 1, nxt = cur ^ 1;

        // prefetch x(t+1) and dis(t+1)
        float disv = 0.0f;
        if (t + 1 < TT) {
            xa = *(const float4*)(nfrow + (size_t)(t + 1) * HH);
            xb = *(const float4*)(nfrow + (size_t)(t + 1) * HH + 4);
            if (tid < GM) disv = g_deg[(grow0 + tid) * TT + t + 1];
        }

        float acc[2][2][3][4];
        #pragma unroll
        for (int p = 0; p < 2; ++p)
            #pragma unroll
            for (int m2 = 0; m2 < 2; ++m2)
                #pragma unroll
                for (int g = 0; g < 3; ++g)
                    #pragma unroll
                    for (int q = 0; q < 4; ++q) acc[p][m2][g][q] = 0.0f;

        const unsigned xbase = xs0 + cur * bufstride + lane_off;
        const unsigned hbase = hs0 + cur * bufstride + lane_off;
        #pragma unroll
        for (int kq = 0; kq < 4; ++kq) {
            #pragma unroll
            for (int m2 = 0; m2 < 2; ++m2) {
                unsigned ax[4], ah[4];
                ldsm4_(ax, xbase + m2 * (16 * HPAD * 2) + kq * 32);
                ldsm4_(ah, hbase + m2 * (16 * HPAD * 2) + kq * 32);
                #pragma unroll
                for (int g = 0; g < 3; ++g) {
                    mma16816(acc[0][m2][g], ax, Bf[0][g][kq]);
                    mma16816(acc[1][m2][g], ah, Bf[1][g][kq]);
                }
            }
        }

        // register epilogue: 8 positions/thread, gates never touch smem
        #pragma unroll
        for (int m2 = 0; m2 < 2; ++m2) {
            #pragma unroll
            for (int rr = 0; rr < 2; ++rr) {
                const int row = m2 * 16 + gid + rr * 8;
                const float dr = dis_s[cur][row];
                float hn2[2];
                #pragma unroll
                for (int c = 0; c < 2; ++c) {
                    const int q = rr * 2 + c;
                    float pr = acc[0][m2][0][q] + acc[1][m2][0][q] + br_[c];
                    float pz = acc[0][m2][1][q] + acc[1][m2][1][q] + bz_[c];
                    float rg = siga_(pr);
                    float zg = siga_(pz);
                    float ng = tanha_(acc[0][m2][2][q] + bnx_[c] +
                                      rg * (acc[1][m2][2][q] + bnh_[c]));
                    const int hi = m2 * 4 + q;
                    float hnew = (1.0f - zg) * ng + zg * h_reg[hi];
                    h_reg[hi] = hnew;
                    hn2[c] = hnew;
                }
                *(unsigned*)&hsm[nxt][row][i0] = bpack(hn2[0], hn2[1]);
                *(unsigned*)&g_buf[((size_t)(grow0 + row) * TT + t) * HH + i0] =
                    bpack(hn2[0] * dr, hn2[1] * dr);
            }
        }

        // stage x(t+1)
        if (t + 1 < TT) {
            unsigned* xp = (unsigned*)&xs[nxt][xrow][xc];
            xp[0] = bpack(xa.x, xa.y); xp[1] = bpack(xa.z, xa.w);
            xp[2] = bpack(xb.x, xb.y); xp[3] = bpack(xb.z, xb.w);
            if (tid < GM) dis_s[nxt][tid] = disv;
        }
        __syncthreads();
    }
}

// ---------------- edge + self-loop gather-reduce ----------------
// g_buf rows pre-scaled by dis[src] (bf16); per-edge factor = ea * dis[dst].
__global__ void scatter_kernel(const int* __restrict__ ei, const float* __restrict__ ea) {
    int gid  = blockIdx.x * blockDim.x + threadIdx.x;
    int item = gid >> 3;
    int part = gid & 7;
    if (item >= EE + NTT) return;
    int rep = blockIdx.x & (REP - 1);

    int src, slot;
    float c;
    if (item < EE) {
        int s = ei[item];
        int d = ei[EE + item];
        c = ea[item] * g_deg[d];
        src = s; slot = slot_of(d);
    } else {
        int i = item - EE;
        c = g_deg[i];
        src = i; slot = slot_of(i);
    }

    const uint4 v = *(const uint4*)&g_buf[src * HH + part * 8];
    float2 f0 = __bfloat1622float2(*(const __nv_bfloat162*)&v.x);
    float2 f1 = __bfloat1622float2(*(const __nv_bfloat162*)&v.y);
    float2 f2 = __bfloat1622float2(*(const __nv_bfloat162*)&v.z);
    float2 f3 = __bfloat1622float2(*(const __nv_bfloat162*)&v.w);

    float* dst = &g_S_rep[rep][slot * HH + part * 8];
    asm volatile("red.global.add.v4.f32 [%0], {%1,%2,%3,%4};"
                 :: "l"(dst), "f"(f0.x * c), "f"(f0.y * c), "f"(f1.x * c), "f"(f1.y * c)
                 : "memory");
    asm volatile("red.global.add.v4.f32 [%0], {%1,%2,%3,%4};"
                 :: "l"(dst + 4), "f"(f2.x * c), "f"(f2.y * c), "f"(f3.x * c), "f"(f3.y * c)
                 : "memory");
}

__global__ void reduce_rep_kernel() {
    int i = blockIdx.x * blockDim.x + threadIdx.x;
    if (i >= NSLOT * HH) return;
    float s = 0.0f;
    #pragma unroll
    for (int r = 0; r < REP; ++r) s += g_S_rep[r][i];
    g_S_pre[i] = s;
}

// ---------------- apply gcn_W (commuted): S = S_pre @ W^T ----------------
__global__ void gcnw_kernel(const float* __restrict__ W) {
    const int s = blockIdx.x;
    const int j = threadIdx.x;
    __shared__ float sp[64];
    sp[j] = g_S_pre[s * HH + j];
    __syncthreads();
    float acc = 0.0f;
    #pragma unroll
    for (int k = 0; k < HH; ++k) acc += sp[k] * W[j * HH + k];
    g_S[s * HH + j] = acc;
}

// ---------------- attention + pooling + head ----------------
__global__ void final_kernel(const float* __restrict__ W1, const float* __restrict__ W2,
                             const float* __restrict__ fcW, const float* __restrict__ fcb,
                             float* __restrict__ out) {
    __shared__ float xt[NSLOT];
    __shared__ float hid[BB * 16];
    __shared__ float attn[NSLOT];
    __shared__ float pooled[BB * HH];

    const int tid = threadIdx.x;   // 256

    {
        float s = 0.0f;
        #pragma unroll
        for (int h = 0; h < HH; ++h) s += g_S[tid * HH + h];
        xt[tid] = s * (1.0f / 32000.0f);
    }
    __syncthreads();

    if (tid < BB * 16) {
        int b = tid >> 4, k = tid & 15;
        float a = 0.0f;
        #pragma unroll
        for (int t = 0; t < TT; ++t) a += xt[b * TT + t] * W1[k * TT + t];
        hid[tid] = fmaxf(a, 0.0f);
    }
    __syncthreads();

    {
        int b = tid >> 5, t = tid & 31;
        float a = 0.0f;
        #pragma unroll
        for (int k = 0; k < 16; ++k) a += hid[b * 16 + k] * W2[t * 16 + k];
        attn[tid] = sigacc_(a);
    }
    __syncthreads();

    for (int idx = tid; idx < BB * HH; idx += 256) {
        int b = idx >> 6, h = idx & 63;
        float a = 0.0f;
        #pragma unroll
        for (int t = 0; t < TT; ++t) a += attn[b * TT + t] * g_S[(b * TT + t) * HH + h];
        pooled[idx] = a;
    }
    __syncthreads();

    if (tid < BB * NSTEPS) {
        int b = tid / NSTEPS, j = tid - b * NSTEPS;
        float a = fcb[j];
        #pragma unroll
        for (int h = 0; h < HH; ++h) a += pooled[b * HH + h] * fcW[j * HH + h];
        out[b * NSTEPS + j] = a;
    }
}

// ---------------- launch ----------------
extern "C" void kernel_launch(void* const* d_in, const int* in_sizes, int n_in,
                              void* d_out, int out_size) {
    const float* nf   = (const float*)d_in[0];
    const int*   ei   = (const int*)  d_in[1];
    const float* ea   = (const float*)d_in[2];
    const float* Wih  = (const float*)d_in[4];
    const float* Whh  = (const float*)d_in[5];
    const float* bih  = (const float*)d_in[6];
    const float* bhh  = (const float*)d_in[7];
    const float* gcnW = (const float*)d_in[8];
    const float* W1   = (const float*)d_in[9];
    const float* W2   = (const float*)d_in[10];
    const float* fcW  = (const float*)d_in[11];
    const float* fcb  = (const float*)d_in[12];
    float* out = (float*)d_out;

    init_kernel<<<(REP * NSLOT * HH + 255) / 256, 256>>>();
    deg_kernel<<<(EE + 255) / 256, 256>>>(ei, ea);
    dis_kernel<<<(NTT + 255) / 256, 256>>>();
    gru_kernel<<<GRU_BLOCKS, 256>>>(nf, Wih, Whh, bih, bhh);
    {
        long items = (long)(EE + NTT) * 8;
        int blocks = (int)((items + 255) / 256);
        scatter_kernel<<<blocks, 256>>>(ei, ea);
    }
    reduce_rep_kernel<<<(NSLOT * HH + 255) / 256, 256>>>();
    gcnw_kernel<<<NSLOT, 64>>>(gcnW);
    final_kernel<<<1, 256>>>(W1, W2, fcW, fcb, out);
}

// round 6
// speedup vs baseline: 3.6119x; 1.3284x over previous
#include <cuda_runtime.h>
#include <cuda_bf16.h>

// Problem constants
#define NN      4000
#define TT      32
#define HH      64
#define G3      192
#define EE      1024000
#define NTT     128000
#define NNEUR   500
#define BB      8
#define NSLOT   256
#define NSTEPS  12
#define NITEMS  (EE + NTT)

#define GM          32     // rows per GRU block
#define GRU_BLOCKS  125
#define HPAD        72     // bf16 row stride (conflict-free ldmatrix)
#define RXT         16     // xt replicas
#define RPL         16     // pooled replicas

// ---------------- device scratch ----------------
__device__ __nv_bfloat16 g_buf[NTT * HH];          // GRU out, pre-scaled by dis
__device__ float g_deg[NTT];                       // degree -> rsqrt in place
__device__ __align__(128) float g_gp[NTT * 16];    // cols 0..11: g@M2, col 12: rho
__device__ float g_Mw[64 * 16];                    // staged M2/wsum table
__device__ float g_tmp[NTT];                       // per-dst scalar accumulation
__device__ __align__(128) float g_xt_rep[RXT][NSLOT];
__device__ float g_attn[NSLOT];
__device__ __align__(128) float g_pool_rep[RPL][BB * NSTEPS];

// ---------------- helpers ----------------
__device__ __forceinline__ float tanha_(float x) {
    float y; asm("tanh.approx.f32 %0, %1;" : "=f"(y) : "f"(x)); return y;
}
__device__ __forceinline__ float siga_(float x) {
    return 0.5f * tanha_(0.5f * x) + 0.5f;
}
__device__ __forceinline__ float sigacc_(float x) {
    return 1.0f / (1.0f + __expf(-x));
}
__device__ __forceinline__ unsigned bpack(float a, float b) {   // {lo=a, hi=b}
    unsigned r;
    asm("cvt.rn.bf16x2.f32 %0, %1, %2;" : "=r"(r) : "f"(b), "f"(a));
    return r;
}
__device__ __forceinline__ void mma16816(float* d, const unsigned* a, const unsigned* b) {
    asm volatile(
        "mma.sync.aligned.m16n8k16.row.col.f32.bf16.bf16.f32 "
        "{%0,%1,%2,%3}, {%4,%5,%6,%7}, {%8,%9}, {%0,%1,%2,%3};"
        : "+f"(d[0]), "+f"(d[1]), "+f"(d[2]), "+f"(d[3])
        : "r"(a[0]), "r"(a[1]), "r"(a[2]), "r"(a[3]), "r"(b[0]), "r"(b[1]));
}
__device__ __forceinline__ void ldsm4_(unsigned* r, unsigned saddr) {
    asm volatile("ldmatrix.sync.aligned.m8n8.x4.shared.b16 {%0,%1,%2,%3}, [%4];"
                 : "=r"(r[0]), "=r"(r[1]), "=r"(r[2]), "=r"(r[3]) : "r"(saddr));
}
__device__ __forceinline__ void redv4_(float* p, float a, float b, float c, float d) {
    asm volatile("red.global.add.v4.f32 [%0], {%1,%2,%3,%4};"
                 :: "l"(p), "f"(a), "f"(b), "f"(c), "f"(d) : "memory");
}

// slot for node-time index nt (torch .view scrambled reshape)
__device__ __forceinline__ int slot_of(int nt) {
    int n = nt >> 5;
    int t = nt & 31;
    int b = n / NNEUR;
    int u = n - b * NNEUR;
    int q = (u << 5) + t;
    return (b << 5) + q / NNEUR;
}

// ---------------- init ----------------
__global__ void init_kernel() {
    int i = blockIdx.x * blockDim.x + threadIdx.x;
    if (i < NTT) { g_deg[i] = 1.0f; g_tmp[i] = 0.0f; }
    if (i < RXT * NSLOT) ((float*)g_xt_rep)[i] = 0.0f;
    if (i < RPL * BB * NSTEPS) ((float*)g_pool_rep)[i] = 0.0f;
}

// ---------------- prep: M2[k][j] = sum_h gcnW[h,k]*fcW[j,h]; col12 = wsum ----
__global__ void prep_kernel(const float* __restrict__ gcnW,
                            const float* __restrict__ fcW) {
    int idx = blockIdx.x * blockDim.x + threadIdx.x;   // 1024 entries
    if (idx >= 64 * 16) return;
    int k = idx >> 4, j = idx & 15;
    float a = 0.0f;
    if (j < NSTEPS) {
        for (int h = 0; h < HH; ++h) a += gcnW[h * HH + k] * fcW[j * HH + h];
    } else if (j == 12) {
        for (int h = 0; h < HH; ++h) a += gcnW[h * HH + k];
    }
    g_Mw[idx] = a;
}

// ---------------- degree / dis ----------------
__global__ void deg_kernel(const int* __restrict__ ei, const float* __restrict__ ea) {
    int e = blockIdx.x * blockDim.x + threadIdx.x;
    if (e < EE) atomicAdd(&g_deg[ei[EE + e]], ea[e]);
}

__global__ void dis_kernel() {
    int i = blockIdx.x * blockDim.x + threadIdx.x;
    if (i < NTT) g_deg[i] = rsqrtf(g_deg[i]);
}

// ---------------- GRU: bf16 mma + ldmatrix + register epilogue ----------------
__global__ void __launch_bounds__(256, 1)
gru_kernel(const float* __restrict__ nf,
           const float* __restrict__ Wih,
           const float* __restrict__ Whh,
           const float* __restrict__ bih,
           const float* __restrict__ bhh) {
    __shared__ __nv_bfloat16 xs[2][GM][HPAD];
    __shared__ __nv_bfloat16 hsm[2][GM][HPAD];
    __shared__ float dis_s[2][GM];

    const int tid  = threadIdx.x;
    const int lane = tid & 31;
    const int w    = tid >> 5;
    const int gid  = lane >> 2;
    const int tig  = lane & 3;
    const int grow0 = blockIdx.x * GM;

    for (int i = tid; i < GM * HPAD; i += 256)
        ((__nv_bfloat16*)hsm[0])[i] = __float2bfloat16(0.0f);

    unsigned Bf[2][3][4][2];
    #pragma unroll
    for (int g = 0; g < 3; ++g) {
        const int ncol = g * 64 + w * 8 + gid;
        #pragma unroll
        for (int kq = 0; kq < 4; ++kq) {
            const int k0 = kq * 16 + 2 * tig;
            Bf[0][g][kq][0] = bpack(Wih[ncol * 64 + k0],     Wih[ncol * 64 + k0 + 1]);
            Bf[0][g][kq][1] = bpack(Wih[ncol * 64 + k0 + 8], Wih[ncol * 64 + k0 + 9]);
            Bf[1][g][kq][0] = bpack(Whh[ncol * 64 + k0],     Whh[ncol * 64 + k0 + 1]);
            Bf[1][g][kq][1] = bpack(Whh[ncol * 64 + k0 + 8], Whh[ncol * 64 + k0 + 9]);
        }
    }

    const int i0 = w * 8 + 2 * tig;
    float br_[2], bz_[2], bnx_[2], bnh_[2];
    #pragma unroll
    for (int c = 0; c < 2; ++c) {
        br_[c]  = bih[i0 + c] + bhh[i0 + c];
        bz_[c]  = bih[64 + i0 + c] + bhh[64 + i0 + c];
        bnx_[c] = bih[128 + i0 + c];
        bnh_[c] = bhh[128 + i0 + c];
    }

    const int xrow = tid >> 3;
    const int xc   = (tid & 7) * 8;
    const float* nfrow = nf + ((size_t)(grow0 + xrow) * TT) * HH + xc;

    float4 xa = *(const float4*)(nfrow);
    float4 xb = *(const float4*)(nfrow + 4);
    {
        unsigned* xp = (unsigned*)&xs[0][xrow][xc];
        xp[0] = bpack(xa.x, xa.y); xp[1] = bpack(xa.z, xa.w);
        xp[2] = bpack(xb.x, xb.y); xp[3] = bpack(xb.z, xb.w);
    }
    if (tid < GM) dis_s[0][tid] = g_deg[(grow0 + tid) * TT + 0];

    const int ro = (lane & 7) + ((lane >> 3) & 1) * 8;
    const int kh = (lane >> 4) & 1;
    const unsigned lane_off = (unsigned)(ro * HPAD * 2 + kh * 16);
    const unsigned xs0 = (unsigned)__cvta_generic_to_shared(&xs[0][0][0]);
    const unsigned hs0 = (unsigned)__cvta_generic_to_shared(&hsm[0][0][0]);
    const unsigned bufstride = GM * HPAD * 2;

    float h_reg[8];
    #pragma unroll
    for (int i = 0; i < 8; ++i) h_reg[i] = 0.0f;

    __syncthreads();

    for (int t = 0; t < TT; ++t) {
        const int cur = t & 1, nxt = cur ^ 1;

        float disv = 0.0f;
        if (t + 1 < TT) {
            xa = *(const float4*)(nfrow + (size_t)(t + 1) * HH);
            xb = *(const float4*)(nfrow + (size_t)(t + 1) * HH + 4);
            if (tid < GM) disv = g_deg[(grow0 + tid) * TT + t + 1];
        }

        float acc[2][2][3][4];
        #pragma unroll
        for (int p = 0; p < 2; ++p)
            #pragma unroll
            for (int m2 = 0; m2 < 2; ++m2)
                #pragma unroll
                for (int g = 0; g < 3; ++g)
                    #pragma unroll
                    for (int q = 0; q < 4; ++q) acc[p][m2][g][q] = 0.0f;

        const unsigned xbase = xs0 + cur * bufstride + lane_off;
        const unsigned hbase = hs0 + cur * bufstride + lane_off;
        #pragma unroll
        for (int kq = 0; kq < 4; ++kq) {
            #pragma unroll
            for (int m2 = 0; m2 < 2; ++m2) {
                unsigned ax[4], ah[4];
                ldsm4_(ax, xbase + m2 * (16 * HPAD * 2) + kq * 32);
                ldsm4_(ah, hbase + m2 * (16 * HPAD * 2) + kq * 32);
                #pragma unroll
                for (int g = 0; g < 3; ++g) {
                    mma16816(acc[0][m2][g], ax, Bf[0][g][kq]);
                    mma16816(acc[1][m2][g], ah, Bf[1][g][kq]);
                }
            }
        }

        #pragma unroll
        for (int m2 = 0; m2 < 2; ++m2) {
            #pragma unroll
            for (int rr = 0; rr < 2; ++rr) {
                const int row = m2 * 16 + gid + rr * 8;
                const float dr = dis_s[cur][row];
                float hn2[2];
                #pragma unroll
                for (int c = 0; c < 2; ++c) {
                    const int q = rr * 2 + c;
                    float pr = acc[0][m2][0][q] + acc[1][m2][0][q] + br_[c];
                    float pz = acc[0][m2][1][q] + acc[1][m2][1][q] + bz_[c];
                    float rg = siga_(pr);
                    float zg = siga_(pz);
                    float ng = tanha_(acc[0][m2][2][q] + bnx_[c] +
                                      rg * (acc[1][m2][2][q] + bnh_[c]));
                    const int hi = m2 * 4 + q;
                    float hnew = (1.0f - zg) * ng + zg * h_reg[hi];
                    h_reg[hi] = hnew;
                    hn2[c] = hnew;
                }
                *(unsigned*)&hsm[nxt][row][i0] = bpack(hn2[0], hn2[1]);
                *(unsigned*)&g_buf[((size_t)(grow0 + row) * TT + t) * HH + i0] =
                    bpack(hn2[0] * dr, hn2[1] * dr);
            }
        }

        if (t + 1 < TT) {
            unsigned* xp = (unsigned*)&xs[nxt][xrow][xc];
            xp[0] = bpack(xa.x, xa.y); xp[1] = bpack(xa.z, xa.w);
            xp[2] = bpack(xb.x, xb.y); xp[3] = bpack(xb.z, xb.w);
            if (tid < GM) dis_s[nxt][tid] = disv;
        }
        __syncthreads();
    }
}

// ---------------- projection: gp[nt][j] = dot(g_buf[nt], Mw[:,j]) --------------
// 64 nodes per block, 4 threads per node (each 4 output cols).
#define PPAD 72
__global__ void __launch_bounds__(256)
proj_kernel() {
    __shared__ __nv_bfloat16 rows[64 * PPAD];
    __shared__ float smW[64 * 16];

    const int tid  = threadIdx.x;
    const int base = blockIdx.x * 64;   // first node

    // stage Mw
    for (int i = tid; i < 64 * 16; i += 256) smW[i] = g_Mw[i];

    // stage 64 rows (8KB) coalesced; smem stride PPAD (16B-aligned stores)
    #pragma unroll
    for (int i = 0; i < 2; ++i) {
        int flat8 = (tid + i * 256) * 8;        // element index (8 bf16 per thread)
        int node = flat8 >> 6, col = flat8 & 63;
        uint4 v = *(const uint4*)&g_buf[(size_t)base * HH + flat8];
        *(uint4*)&rows[node * PPAD + col] = v;
    }
    __syncthreads();

    const int node = tid >> 2;
    const int j0   = (tid & 3) * 4;
    float acc[4] = {0.f, 0.f, 0.f, 0.f};
    #pragma unroll
    for (int k = 0; k < 64; ++k) {
        float xv = __bfloat162float(rows[node * PPAD + k]);
        float4 wv = *(const float4*)&smW[k * 16 + j0];
        acc[0] = fmaf(xv, wv.x, acc[0]);
        acc[1] = fmaf(xv, wv.y, acc[1]);
        acc[2] = fmaf(xv, wv.z, acc[2]);
        acc[3] = fmaf(xv, wv.w, acc[3]);
    }
    float* dst = &g_gp[(size_t)(base + node) * 16 + j0];
    #pragma unroll
    for (int c = 0; c < 4; ++c)
        if (j0 + c < 13) dst[c] = acc[c];
}

// ---------------- scatter1: tmp[dst] += ea * rho[src] --------------------------
__global__ void scatter1_kernel(const int* __restrict__ ei, const float* __restrict__ ea) {
    int e = blockIdx.x * blockDim.x + threadIdx.x;
    if (e >= EE) return;
    int s = ei[e], d = ei[EE + e];
    atomicAdd(&g_tmp[d], ea[e] * g_gp[(size_t)s * 16 + 12]);
}

// ---------------- xt reduce: xt[slot] += dis*(tmp + rho) -----------------------
__global__ void xt_reduce_kernel() {
    int nt = blockIdx.x * blockDim.x + threadIdx.x;
    if (nt >= NTT) return;
    float v = g_deg[nt] * (g_tmp[nt] + g_gp[(size_t)nt * 16 + 12]);
    atomicAdd(&g_xt_rep[nt & (RXT - 1)][slot_of(nt)], v);
}

// ---------------- attn MLP ----------------
__global__ void attn_kernel(const float* __restrict__ W1, const float* __restrict__ W2) {
    __shared__ float xt[NSLOT];
    __shared__ float hid[BB * 16];
    const int tid = threadIdx.x;   // 256

    float s = 0.0f;
    #pragma unroll
    for (int r = 0; r < RXT; ++r) s += g_xt_rep[r][tid];
    xt[tid] = s * (1.0f / 32000.0f);
    __syncthreads();

    if (tid < BB * 16) {
        int b = tid >> 4, k = tid & 15;
        float a = 0.0f;
        #pragma unroll
        for (int t = 0; t < TT; ++t) a += xt[b * TT + t] * W1[k * TT + t];
        hid[tid] = fmaxf(a, 0.0f);
    }
    __syncthreads();

    {
        int b = tid >> 5, t = tid & 31;
        float a = 0.0f;
        #pragma unroll
        for (int k = 0; k < 16; ++k) a += hid[b * 16 + k] * W2[t * 16 + k];
        g_attn[tid] = sigacc_(a);
    }
}

// ---------------- scatter2: pooled12[b] += attn*c*gp[src][0..11] ---------------
#define S2_BLOCKS 296
__global__ void __launch_bounds__(256, 1)
scatter2_kernel(const int* __restrict__ ei, const float* __restrict__ ea) {
    __shared__ float sat[NSLOT];
    const int tid  = threadIdx.x;
    const int lane = tid & 31;
    if (tid < NSLOT) sat[tid] = g_attn[tid];
    __syncthreads();

    float acc[96];
    #pragma unroll
    for (int i = 0; i < 96; ++i) acc[i] = 0.0f;

    const int stride = S2_BLOCKS * 256;
    for (int item = blockIdx.x * 256 + tid; item < NITEMS; item += stride) {
        int src;
        float f;
        int slot;
        if (item < EE) {
            src = ei[item];
            int d = ei[EE + item];
            slot = slot_of(d);
            f = ea[item] * g_deg[d] * sat[slot];
        } else {
            int nt = item - EE;
            src = nt;
            slot = slot_of(nt);
            f = g_deg[nt] * sat[slot];
        }
        const int b = slot >> 5;

        const float4* gp = (const float4*)&g_gp[(size_t)src * 16];
        float4 v0 = gp[0], v1 = gp[1], v2 = gp[2];
        float v[12] = {v0.x, v0.y, v0.z, v0.w, v1.x, v1.y, v1.z, v1.w,
                       v2.x, v2.y, v2.z, v2.w};
        #pragma unroll
        for (int bb = 0; bb < BB; ++bb) {
            float fb = (bb == b) ? f : 0.0f;
            #pragma unroll
            for (int j = 0; j < 12; ++j)
                acc[bb * 12 + j] = fmaf(fb, v[j], acc[bb * 12 + j]);
        }
    }

    // warp butterfly reduce all 96 accumulators
    __syncwarp();
    #pragma unroll
    for (int i = 0; i < 96; ++i) {
        #pragma unroll
        for (int m = 16; m >= 1; m >>= 1)
            acc[i] += __shfl_xor_sync(0xffffffffu, acc[i], m);
    }

    // predicated flush: 24 red.v4 per warp
    const unsigned rep = (blockIdx.x * 8 + (tid >> 5)) & (RPL - 1);
    float* basep = &g_pool_rep[rep][0];
    #pragma unroll
    for (int q = 0; q < 24; ++q)
        if (lane == q)
            redv4_(basep + 4 * q, acc[4 * q], acc[4 * q + 1],
                   acc[4 * q + 2], acc[4 * q + 3]);
}

// ---------------- final: out = pooled12 + fcb ----------------
__global__ void final_kernel(const float* __restrict__ fcb, float* __restrict__ out) {
    int tid = threadIdx.x;
    if (tid >= BB * NSTEPS) return;
    int j = tid % NSTEPS;
    float s = fcb[j];
    #pragma unroll
    for (int r = 0; r < RPL; ++r) s += g_pool_rep[r][tid];
    out[tid] = s;
}

// ---------------- launch ----------------
extern "C" void kernel_launch(void* const* d_in, const int* in_sizes, int n_in,
                              void* d_out, int out_size) {
    const float* nf   = (const float*)d_in[0];
    const int*   ei   = (const int*)  d_in[1];
    const float* ea   = (const float*)d_in[2];
    const float* Wih  = (const float*)d_in[4];
    const float* Whh  = (const float*)d_in[5];
    const float* bih  = (const float*)d_in[6];
    const float* bhh  = (const float*)d_in[7];
    const float* gcnW = (const float*)d_in[8];
    const float* W1   = (const float*)d_in[9];
    const float* W2   = (const float*)d_in[10];
    const float* fcW  = (const float*)d_in[11];
    const float* fcb  = (const float*)d_in[12];
    float* out = (float*)d_out;

    init_kernel<<<(NTT + 255) / 256, 256>>>();
    deg_kernel<<<(EE + 255) / 256, 256>>>(ei, ea);
    dis_kernel<<<(NTT + 255) / 256, 256>>>();
    gru_kernel<<<GRU_BLOCKS, 256>>>(nf, Wih, Whh, bih, bhh);
    prep_kernel<<<4, 256>>>(gcnW, fcW);
    proj_kernel<<<NTT / 64, 256>>>();
    scatter1_kernel<<<(EE + 255) / 256, 256>>>(ei, ea);
    xt_reduce_kernel<<<(NTT + 255) / 256, 256>>>();
    attn_kernel<<<1, 256>>>(W1, W2);
    scatter2_kernel<<<S2_BLOCKS, 256>>>(ei, ea);
    final_kernel<<<1, 128>>>(fcb, out);
}